// round 13
// baseline (speedup 1.0000x reference)
#include <cuda_runtime.h>
#include <cuda_fp16.h>
#include <math.h>
#include <stdint.h>

#define NTOK 16384
#define DMODEL 1024
#define FF 4096
#define NEXP 8
#define CAP 2560
#define NA (NTOK*2)

// ---------------- device scratch (static, allocation-free) ----------------
__device__ __half g_buf[(size_t)NEXP*CAP*DMODEL];
__device__ __half g_h  [(size_t)NEXP*CAP*FF];
__device__ __half g_y  [(size_t)NEXP*CAP*DMODEL];   // fp16 expert outputs
__device__ __half g_w1h[(size_t)NEXP*DMODEL*FF];    // [E][FF][DMODEL] fp16
__device__ __half g_w2h[(size_t)NEXP*FF*DMODEL];    // [E][DMODEL][FF] fp16
__device__ int   g_topi[NA];
__device__ float g_topv[NA];
__device__ int   g_apos[NA];
__device__ int   g_slot_a[NEXP*CAP];
__device__ int   g_kept[NEXP];
__device__ int   g_blkcnt[8][NEXP];

__device__ __forceinline__ void mma_f16(float* d, const uint32_t* a, const uint32_t* b) {
    asm volatile("mma.sync.aligned.m16n8k16.row.col.f32.f16.f16.f32 "
        "{%0,%1,%2,%3}, {%4,%5,%6,%7}, {%8,%9}, {%0,%1,%2,%3};"
        : "+f"(d[0]), "+f"(d[1]), "+f"(d[2]), "+f"(d[3])
        : "r"(a[0]), "r"(a[1]), "r"(a[2]), "r"(a[3]), "r"(b[0]), "r"(b[1]));
}
__device__ __forceinline__ void ldmx4(uint32_t& r0, uint32_t& r1, uint32_t& r2, uint32_t& r3,
                                      uint32_t addr) {
    asm volatile("ldmatrix.sync.aligned.m8n8.x4.shared.b16 {%0,%1,%2,%3}, [%4];"
        : "=r"(r0), "=r"(r1), "=r"(r2), "=r"(r3) : "r"(addr));
}
__device__ __forceinline__ uint32_t smem_u32(const void* p) {
    uint32_t a;
    asm("{ .reg .u64 t; cvta.to.shared.u64 t, %1; cvt.u32.u64 %0, t; }" : "=r"(a) : "l"(p));
    return a;
}
__device__ __forceinline__ void cp16(uint32_t dst, const void* src) {
    asm volatile("cp.async.cg.shared.global [%0], [%1], 16;" :: "r"(dst), "l"(src) : "memory");
}
#define CP_COMMIT() asm volatile("cp.async.commit_group;" ::: "memory")
#define CP_WAIT2()  asm volatile("cp.async.wait_group 2;" ::: "memory")

// Branchless exact-GELU: erf via Abramowitz-Stegun 7.1.26 (|abs err| <= 1.5e-7).
__device__ __forceinline__ float gelu_exact(float t) {
    float s = t * 0.70710678118654752f;
    float a = fabsf(s);
    float den = fmaf(0.3275911f, a, 1.0f);
    float d = __fdividef(1.0f, den);
    float p = fmaf(1.061405429f, d, -1.453152027f);
    p = fmaf(p, d, 1.421413741f);
    p = fmaf(p, d, -0.284496736f);
    p = fmaf(p, d, 0.254829592f);
    p *= d;
    float e = __expf(-s * s);
    float erfa = fmaf(-p, e, 1.0f);
    float erfv = copysignf(erfa, s);
    return 0.5f * t * (1.0f + erfv);
}

// ---------------- fp16 tensor-core grouped GEMM, persistent tile loop --------------
// C[z] = A[z](MxK rm fp16) @ B[z]^T (B stored [N][K] rm fp16) + bias[z].
// flags: bit0 = exact GELU, bit1 = fp16 output (else fp32).
// CTA tile 128(M)x128(N), k-chunk 32, 8 warps (2m x 4n), warp tile 64x32; 2 CTAs/SM.
// Persistent: grid = ~2*SMs, each CTA strides over (bx,by,bz) tiles -> no wave tail.
#define STAGE_BYTES 16384
#define NSTAGE 4
#define PERSIST_GRID 304

__global__ void __launch_bounds__(256, 2) moe_mma_kernel(
    const __half* __restrict__ Ab, const __half* __restrict__ Bb,
    const float* __restrict__ biasb, void* __restrict__ Cb,
    int N, int K, int flags, int ntx, int nty,
    long sA, long sB, long sBias, long sC)
{
    extern __shared__ char smem[];
    const uint32_t sbase = smem_u32(smem);

    const int tid = threadIdx.x;
    const int wid = tid >> 5, lane = tid & 31;
    const int wm = wid >> 2;          // 0..1 -> m offset wm*64
    const int wn = wid & 3;           // 0..3 -> n offset wn*32
    const int g = lane >> 2;
    const int t = lane & 3;

    const int s_row = tid >> 2;
    const int s_c   = tid & 3;
    const int s_cs  = s_c ^ ((s_row >> 1) & 3);

    const int lq = lane >> 3;
    const int lr = lane & 7;
    const int a_frow = wm * 64 + ((lq & 1) << 3) + lr;
    const int a_ks   = lq >> 1;
    const uint32_t a_sw = (a_frow >> 1) & 3;
    const int b_frow = wn * 32 + ((lq >> 1) << 3) + lr;
    const int b_ks   = lq & 1;
    const uint32_t b_sw = (b_frow >> 1) & 3;

    const int nch = K >> 5;
    const int do_gelu = flags & 1, out_half = flags & 2;
    const int ntiles = ntx * nty * NEXP;
    const int ntxy = ntx * nty;

    for (int tile = blockIdx.x; tile < ntiles; tile += gridDim.x) {
        const int bz = tile / ntxy;
        const int rem = tile - bz * ntxy;
        const int by = rem / ntx;
        const int bx = rem - by * ntx;
        const int bm = by * 128;
        const int bn = bx * 128;

        const __half* A = Ab + (size_t)bz * sA;
        const __half* B = Bb + (size_t)bz * sB;
        const float* bias = biasb + (size_t)bz * sBias;

        float acc[4][4][4];
#pragma unroll
        for (int mt = 0; mt < 4; mt++)
#pragma unroll
            for (int nt = 0; nt < 4; nt++)
#pragma unroll
                for (int q = 0; q < 4; q++) acc[mt][nt][q] = 0.f;

        const __half* Agb = A + (size_t)(bm + s_row) * K + s_c * 8;
        const __half* Bgb = B + (size_t)(bn + s_row) * K + s_c * 8;

        // prologue: issue stages 0..2
#pragma unroll
        for (int s = 0; s < NSTAGE - 1; s++) {
            const int k0 = s << 5;
            uint32_t ab = sbase + s * STAGE_BYTES;
#pragma unroll
            for (int l = 0; l < 2; l++)
                cp16(ab + (uint32_t)(((s_row + l * 64) * 4 + s_cs) * 16), Agb + (size_t)l * 64 * K + k0);
            uint32_t bb = ab + 8192;
#pragma unroll
            for (int l = 0; l < 2; l++)
                cp16(bb + (uint32_t)(((s_row + l * 64) * 4 + s_cs) * 16), Bgb + (size_t)l * 64 * K + k0);
            CP_COMMIT();
        }
        CP_WAIT2();
        __syncthreads();

        for (int i = 0; i < nch; i++) {
            const int slot = i & (NSTAGE - 1);
            if (i + NSTAGE - 1 < nch) {
                const int k0 = (i + NSTAGE - 1) << 5;
                uint32_t ab = sbase + ((i + NSTAGE - 1) & (NSTAGE - 1)) * STAGE_BYTES;
#pragma unroll
                for (int l = 0; l < 2; l++)
                    cp16(ab + (uint32_t)(((s_row + l * 64) * 4 + s_cs) * 16), Agb + (size_t)l * 64 * K + k0);
                uint32_t bb = ab + 8192;
#pragma unroll
                for (int l = 0; l < 2; l++)
                    cp16(bb + (uint32_t)(((s_row + l * 64) * 4 + s_cs) * 16), Bgb + (size_t)l * 64 * K + k0);
            }
            CP_COMMIT();

            const uint32_t abase = sbase + slot * STAGE_BYTES + a_frow * 64;
            const uint32_t bbase = sbase + slot * STAGE_BYTES + 8192 + b_frow * 64;
#pragma unroll
            for (int ks = 0; ks < 2; ks++) {
                const uint32_t a_off = (((uint32_t)(2 * ks + a_ks) ^ a_sw) << 4);
                const uint32_t b_off = (((uint32_t)(2 * ks + b_ks) ^ b_sw) << 4);
                uint32_t af[4][4], bf[4][2];
#pragma unroll
                for (int mt = 0; mt < 4; mt++)
                    ldmx4(af[mt][0], af[mt][1], af[mt][2], af[mt][3],
                          abase + mt * 1024 + a_off);
#pragma unroll
                for (int ntp = 0; ntp < 2; ntp++)
                    ldmx4(bf[2*ntp][0], bf[2*ntp][1], bf[2*ntp+1][0], bf[2*ntp+1][1],
                          bbase + ntp * 1024 + b_off);
#pragma unroll
                for (int mt = 0; mt < 4; mt++)
#pragma unroll
                    for (int nt = 0; nt < 4; nt++)
                        mma_f16(acc[mt][nt], af[mt], bf[nt]);
            }
            CP_WAIT2();
            __syncthreads();
        }
        // remaining committed groups are empty -> safe to proceed to next tile

        // ---- epilogue ----
#pragma unroll
        for (int mt = 0; mt < 4; mt++) {
            const int row = bm + wm * 64 + mt * 16 + g;
#pragma unroll
            for (int nt = 0; nt < 4; nt++) {
                const int col = bn + wn * 32 + nt * 8 + 2 * t;
                const float bz0 = bias[col], bz1 = bias[col + 1];
                float v[4] = { acc[mt][nt][0] + bz0, acc[mt][nt][1] + bz1,
                               acc[mt][nt][2] + bz0, acc[mt][nt][3] + bz1 };
                if (do_gelu) {
#pragma unroll
                    for (int q = 0; q < 4; q++) v[q] = gelu_exact(v[q]);
                }
                if (out_half) {
                    __half* C = (__half*)Cb + (size_t)bz * sC;
                    *(__half2*)(C + (size_t)row * N + col)       = __floats2half2_rn(v[0], v[1]);
                    *(__half2*)(C + (size_t)(row + 8) * N + col) = __floats2half2_rn(v[2], v[3]);
                } else {
                    float* C = (float*)Cb + (size_t)bz * sC;
                    *(float2*)(C + (size_t)row * N + col)       = make_float2(v[0], v[1]);
                    *(float2*)(C + (size_t)(row + 8) * N + col) = make_float2(v[2], v[3]);
                }
            }
        }
        __syncthreads();   // protect smem stages from next tile's prologue
    }
}

// ---------------- weight convert + transpose: [E][K][N] fp32 -> [E][N][K] fp16 -------
__global__ void __launch_bounds__(256) convert_w_kernel(const float* __restrict__ in,
                                                        __half* __restrict__ out,
                                                        int K, int N) {
    __shared__ float tile[32][65];
    const float* w = in + (size_t)blockIdx.z * K * N;
    __half* o = out + (size_t)blockIdx.z * N * K;
    int n0 = blockIdx.x * 32, k0 = blockIdx.y * 64;
    int tx = threadIdx.x & 31, ty = threadIdx.x >> 5;
#pragma unroll
    for (int i = 0; i < 8; i++) {
        int k = ty + i * 8;
        tile[tx][k] = w[(size_t)(k0 + k) * N + n0 + tx];
    }
    __syncthreads();
#pragma unroll
    for (int i = 0; i < 4; i++) {
        int n = ty * 4 + i;
        __half2 h = __floats2half2_rn(tile[n][2 * tx], tile[n][2 * tx + 1]);
        *(__half2*)(o + (size_t)(n0 + n) * K + k0 + 2 * tx) = h;
    }
}

// ---------------- router ----------------
__global__ void __launch_bounds__(256) router_kernel(const float* __restrict__ x,
                                                     const float* __restrict__ wr,
                                                     const float* __restrict__ br) {
    __shared__ float swT[NEXP][DMODEL];
    int tid = threadIdx.x;
    for (int i = tid; i < DMODEL * NEXP; i += 256) {
        int d = i >> 3, e = i & 7;
        swT[e][d] = wr[i];
    }
    __syncthreads();
    int warp = tid >> 5, lane = tid & 31;
    int token = blockIdx.x * 8 + warp;
    const float* xr = x + (size_t)token * DMODEL;
    float p[NEXP];
#pragma unroll
    for (int e = 0; e < NEXP; e++) p[e] = 0.f;
    for (int j = lane; j < DMODEL; j += 32) {
        float xv = xr[j];
#pragma unroll
        for (int e = 0; e < NEXP; e++) p[e] = fmaf(xv, swT[e][j], p[e]);
    }
#pragma unroll
    for (int e = 0; e < NEXP; e++) {
#pragma unroll
        for (int off = 16; off; off >>= 1)
            p[e] += __shfl_xor_sync(0xffffffffu, p[e], off);
    }
    if (lane == 0) {
        float mx = -1e30f;
#pragma unroll
        for (int e = 0; e < NEXP; e++) { p[e] += br[e]; mx = fmaxf(mx, p[e]); }
        float s = 0.f;
#pragma unroll
        for (int e = 0; e < NEXP; e++) { p[e] = expf(p[e] - mx); s += p[e]; }
        float inv = 1.f / s;
#pragma unroll
        for (int e = 0; e < NEXP; e++) p[e] *= inv;
        int b0 = 0; float v0 = p[0];
#pragma unroll
        for (int e = 1; e < NEXP; e++) if (p[e] > v0) { v0 = p[e]; b0 = e; }
        int b1 = -1; float v1 = -1.f;
#pragma unroll
        for (int e = 0; e < NEXP; e++) if (e != b0 && p[e] > v1) { v1 = p[e]; b1 = e; }
        g_topi[token*2]   = b0;  g_topv[token*2]   = v0;
        g_topi[token*2+1] = b1;  g_topv[token*2+1] = v1;
    }
}

// ---------------- scan stage 1: per-block expert counts ----------------
__global__ void __launch_bounds__(1024) scan_count_kernel() {
    const int tid = threadIdx.x, wid = tid >> 5, lane = tid & 31;
    int4 v = ((const int4*)g_topi)[blockIdx.x * 1024 + tid];
    uint64_t hc = (1ULL << (v.x * 8)) + (1ULL << (v.y * 8))
                + (1ULL << (v.z * 8)) + (1ULL << (v.w * 8));
#pragma unroll
    for (int off = 16; off; off >>= 1)
        hc += __shfl_xor_sync(0xffffffffu, hc, off);
    __shared__ uint64_t wlo[32], whi[32];
    if (lane == 0) {
        uint64_t lo = 0, hi = 0;
#pragma unroll
        for (int e = 0; e < 4; e++) lo |= ((hc >> (e * 8)) & 0xff) << (e * 16);
#pragma unroll
        for (int e = 4; e < 8; e++) hi |= ((hc >> (e * 8)) & 0xff) << ((e - 4) * 16);
        wlo[wid] = lo; whi[wid] = hi;
    }
    __syncthreads();
    if (wid == 0) {
        uint64_t lo = wlo[lane], hi = whi[lane];
#pragma unroll
        for (int off = 16; off; off >>= 1) {
            lo += __shfl_xor_sync(0xffffffffu, lo, off);
            hi += __shfl_xor_sync(0xffffffffu, hi, off);
        }
        if (lane < 4)      g_blkcnt[blockIdx.x][lane] = (int)((lo >> (lane * 16)) & 0xffff);
        else if (lane < 8) g_blkcnt[blockIdx.x][lane] = (int)((hi >> ((lane - 4) * 16)) & 0xffff);
    }
}

// ---------------- scan stage 2: block-local scan + scatter ----------------
__global__ void __launch_bounds__(1024) scan_scatter_kernel() {
    __shared__ int scnt[NEXP][1024];
    const int tid = threadIdx.x, wid = tid >> 5, lane = tid & 31;
    int4 v = ((const int4*)g_topi)[blockIdx.x * 1024 + tid];
    uint64_t hc = (1ULL << (v.x * 8)) + (1ULL << (v.y * 8))
                + (1ULL << (v.z * 8)) + (1ULL << (v.w * 8));
#pragma unroll
    for (int e = 0; e < NEXP; e++)
        scnt[e][tid] = (int)((hc >> (e * 8)) & 0xff);
    __syncthreads();

    if (wid < NEXP) {
        const int e = wid;
        int run = 0;
        for (int b = 0; b < 8; b++) {
            int c = g_blkcnt[b][e];
            if (b < blockIdx.x) run += c;
        }
        if (blockIdx.x == 0 && lane == 0) {
            int tot = 0;
#pragma unroll
            for (int b = 0; b < 8; b++) tot += g_blkcnt[b][e];
            g_kept[e] = tot < CAP ? tot : CAP;
        }
#pragma unroll 4
        for (int r = 0; r < 32; r++) {
            int val = scnt[e][r * 32 + lane];
            int x = val;
#pragma unroll
            for (int off = 1; off < 32; off <<= 1) {
                int y = __shfl_up_sync(0xffffffffu, x, off);
                if (lane >= off) x += y;
            }
            scnt[e][r * 32 + lane] = run + x - val;
            run += __shfl_sync(0xffffffffu, x, 31);
        }
    }
    __syncthreads();

    uint64_t b0 = 0, b1 = 0;
#pragma unroll
    for (int e = 0; e < 4; e++) b0 |= (uint64_t)(uint32_t)scnt[e][tid] << (e * 16);
#pragma unroll
    for (int e = 4; e < 8; e++) b1 |= (uint64_t)(uint32_t)scnt[e][tid] << ((e - 4) * 16);

    const int a0 = blockIdx.x * 4096 + tid * 4;
    int ids[4] = { v.x, v.y, v.z, v.w };
#pragma unroll
    for (int j = 0; j < 4; j++) {
        const int e = ids[j];
        const int a = a0 + j;
        const int sh = (e & 3) * 16;
        uint64_t w = (e < 4) ? b0 : b1;
        const int pos = (int)((w >> sh) & 0xffff);
        w += 1ULL << sh;
        if (e < 4) b0 = w; else b1 = w;
        if (pos < CAP) { g_apos[a] = pos; g_slot_a[e * CAP + pos] = a; }
        else           { g_apos[a] = -1; }
    }
}

// ---------------- dispatch gather (fp32 -> fp16 activations) ----------------
__global__ void __launch_bounds__(256) dispatch_kernel(const float* __restrict__ x) {
    int r = blockIdx.x;
    int e = r / CAP, pos = r - e * CAP;
    uint2* dst = (uint2*)(g_buf + (size_t)r * DMODEL);
    if (pos < g_kept[e]) {
        int a = g_slot_a[r];
        float4 v = ((const float4*)(x + (size_t)(a >> 1) * DMODEL))[threadIdx.x];
        __half2 h0 = __floats2half2_rn(v.x, v.y);
        __half2 h1 = __floats2half2_rn(v.z, v.w);
        uint2 u;
        u.x = *reinterpret_cast<uint32_t*>(&h0);
        u.y = *reinterpret_cast<uint32_t*>(&h1);
        dst[threadIdx.x] = u;
    } else {
        dst[threadIdx.x] = make_uint2(0u, 0u);
    }
}

// ---------------- combine (fp16 expert outputs) ----------------
__global__ void __launch_bounds__(256) combine_kernel(float* __restrict__ out) {
    int token = blockIdx.x;
    int a0 = token * 2;
    int p0 = g_apos[a0], p1 = g_apos[a0 + 1];
    float w0 = (p0 >= 0) ? g_topv[a0]     : 0.f;
    float w1 = (p1 >= 0) ? g_topv[a0 + 1] : 0.f;
    float ws = w0 + w1;
    int t4 = threadIdx.x;
    float4 acc = make_float4(0.f, 0.f, 0.f, 0.f);
    if (p0 >= 0) {
        uint2 u = ((const uint2*)(g_y + ((size_t)g_topi[a0] * CAP + p0) * DMODEL))[t4];
        float2 fa = __half22float2(*(__half2*)&u.x);
        float2 fb = __half22float2(*(__half2*)&u.y);
        acc.x = fmaf(w0, fa.x, acc.x); acc.y = fmaf(w0, fa.y, acc.y);
        acc.z = fmaf(w0, fb.x, acc.z); acc.w = fmaf(w0, fb.y, acc.w);
    }
    if (p1 >= 0) {
        uint2 u = ((const uint2*)(g_y + ((size_t)g_topi[a0 + 1] * CAP + p1) * DMODEL))[t4];
        float2 fa = __half22float2(*(__half2*)&u.x);
        float2 fb = __half22float2(*(__half2*)&u.y);
        acc.x = fmaf(w1, fa.x, acc.x); acc.y = fmaf(w1, fa.y, acc.y);
        acc.z = fmaf(w1, fb.x, acc.z); acc.w = fmaf(w1, fb.y, acc.w);
    }
    if (ws > 0.f) {
        float inv = 1.f / fmaxf(ws, 1e-6f);
        acc.x *= inv; acc.y *= inv; acc.z *= inv; acc.w *= inv;
    }
    ((float4*)(out + (size_t)token * DMODEL))[t4] = acc;
}

// ---------------- launch ----------------
#define SMEM_TOTAL (NSTAGE * STAGE_BYTES)   // 64 KB per CTA

extern "C" void kernel_launch(void* const* d_in, const int* in_sizes, int n_in,
                              void* d_out, int out_size) {
    const float* x  = (const float*)d_in[0];
    const float* wr = (const float*)d_in[1];
    const float* br = (const float*)d_in[2];
    const float* w1 = (const float*)d_in[3];
    const float* b1 = (const float*)d_in[4];
    const float* w2 = (const float*)d_in[5];
    const float* b2 = (const float*)d_in[6];
    float* y = (float*)d_out;

    __half *buf, *h, *yy, *w1h, *w2h;
    cudaGetSymbolAddress((void**)&buf, g_buf);
    cudaGetSymbolAddress((void**)&h,   g_h);
    cudaGetSymbolAddress((void**)&yy,  g_y);
    cudaGetSymbolAddress((void**)&w1h, g_w1h);
    cudaGetSymbolAddress((void**)&w2h, g_w2h);

    cudaFuncSetAttribute(moe_mma_kernel, cudaFuncAttributeMaxDynamicSharedMemorySize, SMEM_TOTAL);

    convert_w_kernel<<<dim3(FF / 32, DMODEL / 64, NEXP), 256>>>(w1, w1h, DMODEL, FF);
    convert_w_kernel<<<dim3(DMODEL / 32, FF / 64, NEXP), 256>>>(w2, w2h, FF, DMODEL);

    router_kernel<<<NTOK / 8, 256>>>(x, wr, br);
    scan_count_kernel<<<8, 1024>>>();
    scan_scatter_kernel<<<8, 1024>>>();
    dispatch_kernel<<<NEXP * CAP, 256>>>(x);

    // GEMM1: h = fp16(GELU(buf @ w1 + b1)); tiles 32(N) x 20(M) x 8(E)
    moe_mma_kernel<<<PERSIST_GRID, 256, SMEM_TOTAL>>>(buf, w1h, b1, (void*)h,
                              FF, DMODEL, 3, FF / 128, CAP / 128,
                              (long)CAP * DMODEL, (long)DMODEL * FF, FF, (long)CAP * FF);

    // GEMM2: y_e = fp16(h @ w2 + b2); tiles 8(N) x 20(M) x 8(E)
    moe_mma_kernel<<<PERSIST_GRID, 256, SMEM_TOTAL>>>(h, w2h, b2, (void*)yy,
                              DMODEL, FF, 2, DMODEL / 128, CAP / 128,
                              (long)CAP * FF, (long)FF * DMODEL, DMODEL, (long)CAP * DMODEL);

    combine_kernel<<<NTOK, 256>>>(y);
}

// round 14
// speedup vs baseline: 1.0310x; 1.0310x over previous
#include <cuda_runtime.h>
#include <cuda_fp16.h>
#include <math.h>
#include <stdint.h>

#define NTOK 16384
#define DMODEL 1024
#define FF 4096
#define NEXP 8
#define CAP 2560
#define NA (NTOK*2)

// ---------------- device scratch (static, allocation-free) ----------------
__device__ __half g_buf[(size_t)NEXP*CAP*DMODEL];
__device__ __half g_h  [(size_t)NEXP*CAP*FF];
__device__ __half g_y  [(size_t)NEXP*CAP*DMODEL];   // fp16 expert outputs
__device__ __half g_w1h[(size_t)NEXP*DMODEL*FF];    // [E][FF][DMODEL] fp16
__device__ __half g_w2h[(size_t)NEXP*FF*DMODEL];    // [E][DMODEL][FF] fp16
__device__ int   g_topi[NA];
__device__ float g_topv[NA];
__device__ int   g_apos[NA];
__device__ int   g_slot_a[NEXP*CAP];
__device__ int   g_kept[NEXP];
__device__ int   g_blkcnt[8][NEXP];

__device__ __forceinline__ void mma_f16(float* d, const uint32_t* a, const uint32_t* b) {
    asm volatile("mma.sync.aligned.m16n8k16.row.col.f32.f16.f16.f32 "
        "{%0,%1,%2,%3}, {%4,%5,%6,%7}, {%8,%9}, {%0,%1,%2,%3};"
        : "+f"(d[0]), "+f"(d[1]), "+f"(d[2]), "+f"(d[3])
        : "r"(a[0]), "r"(a[1]), "r"(a[2]), "r"(a[3]), "r"(b[0]), "r"(b[1]));
}
__device__ __forceinline__ void ldmx4(uint32_t& r0, uint32_t& r1, uint32_t& r2, uint32_t& r3,
                                      uint32_t addr) {
    asm volatile("ldmatrix.sync.aligned.m8n8.x4.shared.b16 {%0,%1,%2,%3}, [%4];"
        : "=r"(r0), "=r"(r1), "=r"(r2), "=r"(r3) : "r"(addr));
}
__device__ __forceinline__ uint32_t smem_u32(const void* p) {
    uint32_t a;
    asm("{ .reg .u64 t; cvta.to.shared.u64 t, %1; cvt.u32.u64 %0, t; }" : "=r"(a) : "l"(p));
    return a;
}
__device__ __forceinline__ void cp16(uint32_t dst, const void* src) {
    asm volatile("cp.async.cg.shared.global [%0], [%1], 16;" :: "r"(dst), "l"(src) : "memory");
}
#define CP_COMMIT() asm volatile("cp.async.commit_group;" ::: "memory")
#define CP_WAIT2()  asm volatile("cp.async.wait_group 2;" ::: "memory")

// Branchless exact-GELU: erf via Abramowitz-Stegun 7.1.26 (|abs err| <= 1.5e-7).
__device__ __forceinline__ float gelu_exact(float t) {
    float s = t * 0.70710678118654752f;
    float a = fabsf(s);
    float den = fmaf(0.3275911f, a, 1.0f);
    float d = __fdividef(1.0f, den);
    float p = fmaf(1.061405429f, d, -1.453152027f);
    p = fmaf(p, d, 1.421413741f);
    p = fmaf(p, d, -0.284496736f);
    p = fmaf(p, d, 0.254829592f);
    p *= d;
    float e = __expf(-s * s);
    float erfa = fmaf(-p, e, 1.0f);
    float erfv = copysignf(erfa, s);
    return 0.5f * t * (1.0f + erfv);
}

// ---------------- fp16 tensor-core grouped GEMM, 4-stage cp.async + ldmatrix --------
// C[z] = A[z](MxK rm fp16) @ B[z]^T (B stored [N][K] rm fp16) + bias[z].
// flags: bit0 = exact GELU, bit1 = fp16 output (else fp32).
// CTA tile 128(M)x128(N), k-chunk 32, 8 warps (2m x 4n), warp tile 64x32; 2 CTAs/SM.
#define STAGE_BYTES 16384
#define NSTAGE 4

__global__ void __launch_bounds__(256, 2) moe_mma_kernel(
    const __half* __restrict__ Ab, const __half* __restrict__ Bb,
    const float* __restrict__ biasb, void* __restrict__ Cb,
    int N, int K, int flags,
    long sA, long sB, long sBias, long sC)
{
    extern __shared__ char smem[];
    const uint32_t sbase = smem_u32(smem);

    const __half* A = Ab + (size_t)blockIdx.z * sA;
    const __half* B = Bb + (size_t)blockIdx.z * sB;
    const float* bias = biasb + (size_t)blockIdx.z * sBias;

    const int tid = threadIdx.x;
    const int wid = tid >> 5, lane = tid & 31;
    const int wm = wid >> 2;          // 0..1 -> m offset wm*64
    const int wn = wid & 3;           // 0..3 -> n offset wn*32
    const int g = lane >> 2;
    const int t = lane & 3;
    const int bm = blockIdx.y * 128;
    const int bn = blockIdx.x * 128;

    const int s_row = tid >> 2;
    const int s_c   = tid & 3;
    const int s_cs  = s_c ^ ((s_row >> 1) & 3);

    const int lq = lane >> 3;
    const int lr = lane & 7;
    const int a_frow = wm * 64 + ((lq & 1) << 3) + lr;
    const int a_ks   = lq >> 1;
    const uint32_t a_sw = (a_frow >> 1) & 3;
    const int b_frow = wn * 32 + ((lq >> 1) << 3) + lr;
    const int b_ks   = lq & 1;
    const uint32_t b_sw = (b_frow >> 1) & 3;

    float acc[4][4][4];
#pragma unroll
    for (int mt = 0; mt < 4; mt++)
#pragma unroll
        for (int nt = 0; nt < 4; nt++)
#pragma unroll
            for (int q = 0; q < 4; q++) acc[mt][nt][q] = 0.f;

    const int nch = K >> 5;
    const __half* Agb = A + (size_t)(bm + s_row) * K + s_c * 8;
    const __half* Bgb = B + (size_t)(bn + s_row) * K + s_c * 8;

    // prologue: issue stages 0..2
#pragma unroll
    for (int s = 0; s < NSTAGE - 1; s++) {
        const int k0 = s << 5;
        uint32_t ab = sbase + s * STAGE_BYTES;
#pragma unroll
        for (int l = 0; l < 2; l++)
            cp16(ab + (uint32_t)(((s_row + l * 64) * 4 + s_cs) * 16), Agb + (size_t)l * 64 * K + k0);
        uint32_t bb = ab + 8192;
#pragma unroll
        for (int l = 0; l < 2; l++)
            cp16(bb + (uint32_t)(((s_row + l * 64) * 4 + s_cs) * 16), Bgb + (size_t)l * 64 * K + k0);
        CP_COMMIT();
    }
    CP_WAIT2();
    __syncthreads();

    for (int i = 0; i < nch; i++) {
        const int slot = i & (NSTAGE - 1);
        if (i + NSTAGE - 1 < nch) {
            const int k0 = (i + NSTAGE - 1) << 5;
            uint32_t ab = sbase + ((i + NSTAGE - 1) & (NSTAGE - 1)) * STAGE_BYTES;
#pragma unroll
            for (int l = 0; l < 2; l++)
                cp16(ab + (uint32_t)(((s_row + l * 64) * 4 + s_cs) * 16), Agb + (size_t)l * 64 * K + k0);
            uint32_t bb = ab + 8192;
#pragma unroll
            for (int l = 0; l < 2; l++)
                cp16(bb + (uint32_t)(((s_row + l * 64) * 4 + s_cs) * 16), Bgb + (size_t)l * 64 * K + k0);
        }
        CP_COMMIT();

        const uint32_t abase = sbase + slot * STAGE_BYTES + a_frow * 64;
        const uint32_t bbase = sbase + slot * STAGE_BYTES + 8192 + b_frow * 64;
#pragma unroll
        for (int ks = 0; ks < 2; ks++) {
            const uint32_t a_off = (((uint32_t)(2 * ks + a_ks) ^ a_sw) << 4);
            const uint32_t b_off = (((uint32_t)(2 * ks + b_ks) ^ b_sw) << 4);
            uint32_t af[4][4], bf[4][2];
#pragma unroll
            for (int mt = 0; mt < 4; mt++)
                ldmx4(af[mt][0], af[mt][1], af[mt][2], af[mt][3],
                      abase + mt * 1024 + a_off);
#pragma unroll
            for (int ntp = 0; ntp < 2; ntp++)
                ldmx4(bf[2*ntp][0], bf[2*ntp][1], bf[2*ntp+1][0], bf[2*ntp+1][1],
                      bbase + ntp * 1024 + b_off);
#pragma unroll
            for (int mt = 0; mt < 4; mt++)
#pragma unroll
                for (int nt = 0; nt < 4; nt++)
                    mma_f16(acc[mt][nt], af[mt], bf[nt]);
        }
        CP_WAIT2();
        __syncthreads();
    }

    // ---- epilogue ----
    const int do_gelu = flags & 1, out_half = flags & 2;
#pragma unroll
    for (int mt = 0; mt < 4; mt++) {
        const int row = bm + wm * 64 + mt * 16 + g;
#pragma unroll
        for (int nt = 0; nt < 4; nt++) {
            const int col = bn + wn * 32 + nt * 8 + 2 * t;
            const float bz0 = bias[col], bz1 = bias[col + 1];
            float v[4] = { acc[mt][nt][0] + bz0, acc[mt][nt][1] + bz1,
                           acc[mt][nt][2] + bz0, acc[mt][nt][3] + bz1 };
            if (do_gelu) {
#pragma unroll
                for (int q = 0; q < 4; q++) v[q] = gelu_exact(v[q]);
            }
            if (out_half) {
                __half* C = (__half*)Cb + (size_t)blockIdx.z * sC;
                *(__half2*)(C + (size_t)row * N + col)       = __floats2half2_rn(v[0], v[1]);
                *(__half2*)(C + (size_t)(row + 8) * N + col) = __floats2half2_rn(v[2], v[3]);
            } else {
                float* C = (float*)Cb + (size_t)blockIdx.z * sC;
                *(float2*)(C + (size_t)row * N + col)       = make_float2(v[0], v[1]);
                *(float2*)(C + (size_t)(row + 8) * N + col) = make_float2(v[2], v[3]);
            }
        }
    }
}

// ---------------- weight convert + transpose: [E][K][N] fp32 -> [E][N][K] fp16 -------
__global__ void __launch_bounds__(256) convert_w_kernel(const float* __restrict__ in,
                                                        __half* __restrict__ out,
                                                        int K, int N) {
    __shared__ float tile[32][65];
    const float* w = in + (size_t)blockIdx.z * K * N;
    __half* o = out + (size_t)blockIdx.z * N * K;
    int n0 = blockIdx.x * 32, k0 = blockIdx.y * 64;
    int tx = threadIdx.x & 31, ty = threadIdx.x >> 5;
#pragma unroll
    for (int i = 0; i < 8; i++) {
        int k = ty + i * 8;
        tile[tx][k] = w[(size_t)(k0 + k) * N + n0 + tx];
    }
    __syncthreads();
#pragma unroll
    for (int i = 0; i < 4; i++) {
        int n = ty * 4 + i;
        __half2 h = __floats2half2_rn(tile[n][2 * tx], tile[n][2 * tx + 1]);
        *(__half2*)(o + (size_t)(n0 + n) * K + k0 + 2 * tx) = h;
    }
}

// ---------------- router ----------------
__global__ void __launch_bounds__(256) router_kernel(const float* __restrict__ x,
                                                     const float* __restrict__ wr,
                                                     const float* __restrict__ br) {
    __shared__ float swT[NEXP][DMODEL];
    int tid = threadIdx.x;
    for (int i = tid; i < DMODEL * NEXP; i += 256) {
        int d = i >> 3, e = i & 7;
        swT[e][d] = wr[i];
    }
    __syncthreads();
    int warp = tid >> 5, lane = tid & 31;
    int token = blockIdx.x * 8 + warp;
    const float* xr = x + (size_t)token * DMODEL;
    float p[NEXP];
#pragma unroll
    for (int e = 0; e < NEXP; e++) p[e] = 0.f;
    for (int j = lane; j < DMODEL; j += 32) {
        float xv = xr[j];
#pragma unroll
        for (int e = 0; e < NEXP; e++) p[e] = fmaf(xv, swT[e][j], p[e]);
    }
#pragma unroll
    for (int e = 0; e < NEXP; e++) {
#pragma unroll
        for (int off = 16; off; off >>= 1)
            p[e] += __shfl_xor_sync(0xffffffffu, p[e], off);
    }
    if (lane == 0) {
        float mx = -1e30f;
#pragma unroll
        for (int e = 0; e < NEXP; e++) { p[e] += br[e]; mx = fmaxf(mx, p[e]); }
        float s = 0.f;
#pragma unroll
        for (int e = 0; e < NEXP; e++) { p[e] = expf(p[e] - mx); s += p[e]; }
        float inv = 1.f / s;
#pragma unroll
        for (int e = 0; e < NEXP; e++) p[e] *= inv;
        int b0 = 0; float v0 = p[0];
#pragma unroll
        for (int e = 1; e < NEXP; e++) if (p[e] > v0) { v0 = p[e]; b0 = e; }
        int b1 = -1; float v1 = -1.f;
#pragma unroll
        for (int e = 0; e < NEXP; e++) if (e != b0 && p[e] > v1) { v1 = p[e]; b1 = e; }
        g_topi[token*2]   = b0;  g_topv[token*2]   = v0;
        g_topi[token*2+1] = b1;  g_topv[token*2+1] = v1;
    }
}

// ---------------- scan stage 1: per-block expert counts ----------------
__global__ void __launch_bounds__(1024) scan_count_kernel() {
    const int tid = threadIdx.x, wid = tid >> 5, lane = tid & 31;
    int4 v = ((const int4*)g_topi)[blockIdx.x * 1024 + tid];
    uint64_t hc = (1ULL << (v.x * 8)) + (1ULL << (v.y * 8))
                + (1ULL << (v.z * 8)) + (1ULL << (v.w * 8));
#pragma unroll
    for (int off = 16; off; off >>= 1)
        hc += __shfl_xor_sync(0xffffffffu, hc, off);
    __shared__ uint64_t wlo[32], whi[32];
    if (lane == 0) {
        uint64_t lo = 0, hi = 0;
#pragma unroll
        for (int e = 0; e < 4; e++) lo |= ((hc >> (e * 8)) & 0xff) << (e * 16);
#pragma unroll
        for (int e = 4; e < 8; e++) hi |= ((hc >> (e * 8)) & 0xff) << ((e - 4) * 16);
        wlo[wid] = lo; whi[wid] = hi;
    }
    __syncthreads();
    if (wid == 0) {
        uint64_t lo = wlo[lane], hi = whi[lane];
#pragma unroll
        for (int off = 16; off; off >>= 1) {
            lo += __shfl_xor_sync(0xffffffffu, lo, off);
            hi += __shfl_xor_sync(0xffffffffu, hi, off);
        }
        if (lane < 4)      g_blkcnt[blockIdx.x][lane] = (int)((lo >> (lane * 16)) & 0xffff);
        else if (lane < 8) g_blkcnt[blockIdx.x][lane] = (int)((hi >> ((lane - 4) * 16)) & 0xffff);
    }
}

// ---------------- scan stage 2: block-local scan + scatter ----------------
__global__ void __launch_bounds__(1024) scan_scatter_kernel() {
    __shared__ int scnt[NEXP][1024];
    const int tid = threadIdx.x, wid = tid >> 5, lane = tid & 31;
    int4 v = ((const int4*)g_topi)[blockIdx.x * 1024 + tid];
    uint64_t hc = (1ULL << (v.x * 8)) + (1ULL << (v.y * 8))
                + (1ULL << (v.z * 8)) + (1ULL << (v.w * 8));
#pragma unroll
    for (int e = 0; e < NEXP; e++)
        scnt[e][tid] = (int)((hc >> (e * 8)) & 0xff);
    __syncthreads();

    if (wid < NEXP) {
        const int e = wid;
        int run = 0;
        for (int b = 0; b < 8; b++) {
            int c = g_blkcnt[b][e];
            if (b < blockIdx.x) run += c;
        }
        if (blockIdx.x == 0 && lane == 0) {
            int tot = 0;
#pragma unroll
            for (int b = 0; b < 8; b++) tot += g_blkcnt[b][e];
            g_kept[e] = tot < CAP ? tot : CAP;
        }
#pragma unroll 4
        for (int r = 0; r < 32; r++) {
            int val = scnt[e][r * 32 + lane];
            int x = val;
#pragma unroll
            for (int off = 1; off < 32; off <<= 1) {
                int y = __shfl_up_sync(0xffffffffu, x, off);
                if (lane >= off) x += y;
            }
            scnt[e][r * 32 + lane] = run + x - val;
            run += __shfl_sync(0xffffffffu, x, 31);
        }
    }
    __syncthreads();

    uint64_t b0 = 0, b1 = 0;
#pragma unroll
    for (int e = 0; e < 4; e++) b0 |= (uint64_t)(uint32_t)scnt[e][tid] << (e * 16);
#pragma unroll
    for (int e = 4; e < 8; e++) b1 |= (uint64_t)(uint32_t)scnt[e][tid] << ((e - 4) * 16);

    const int a0 = blockIdx.x * 4096 + tid * 4;
    int ids[4] = { v.x, v.y, v.z, v.w };
#pragma unroll
    for (int j = 0; j < 4; j++) {
        const int e = ids[j];
        const int a = a0 + j;
        const int sh = (e & 3) * 16;
        uint64_t w = (e < 4) ? b0 : b1;
        const int pos = (int)((w >> sh) & 0xffff);
        w += 1ULL << sh;
        if (e < 4) b0 = w; else b1 = w;
        if (pos < CAP) { g_apos[a] = pos; g_slot_a[e * CAP + pos] = a; }
        else           { g_apos[a] = -1; }
    }
}

// ---------------- dispatch gather (fp32 -> fp16 activations) ----------------
__global__ void __launch_bounds__(256) dispatch_kernel(const float* __restrict__ x) {
    int r = blockIdx.x;
    int e = r / CAP, pos = r - e * CAP;
    uint2* dst = (uint2*)(g_buf + (size_t)r * DMODEL);
    if (pos < g_kept[e]) {
        int a = g_slot_a[r];
        float4 v = ((const float4*)(x + (size_t)(a >> 1) * DMODEL))[threadIdx.x];
        __half2 h0 = __floats2half2_rn(v.x, v.y);
        __half2 h1 = __floats2half2_rn(v.z, v.w);
        uint2 u;
        u.x = *reinterpret_cast<uint32_t*>(&h0);
        u.y = *reinterpret_cast<uint32_t*>(&h1);
        dst[threadIdx.x] = u;
    } else {
        dst[threadIdx.x] = make_uint2(0u, 0u);
    }
}

// ---------------- combine (fp16 expert outputs) ----------------
__global__ void __launch_bounds__(256) combine_kernel(float* __restrict__ out) {
    int token = blockIdx.x;
    int a0 = token * 2;
    int p0 = g_apos[a0], p1 = g_apos[a0 + 1];
    float w0 = (p0 >= 0) ? g_topv[a0]     : 0.f;
    float w1 = (p1 >= 0) ? g_topv[a0 + 1] : 0.f;
    float ws = w0 + w1;
    int t4 = threadIdx.x;
    float4 acc = make_float4(0.f, 0.f, 0.f, 0.f);
    if (p0 >= 0) {
        uint2 u = ((const uint2*)(g_y + ((size_t)g_topi[a0] * CAP + p0) * DMODEL))[t4];
        float2 fa = __half22float2(*(__half2*)&u.x);
        float2 fb = __half22float2(*(__half2*)&u.y);
        acc.x = fmaf(w0, fa.x, acc.x); acc.y = fmaf(w0, fa.y, acc.y);
        acc.z = fmaf(w0, fb.x, acc.z); acc.w = fmaf(w0, fb.y, acc.w);
    }
    if (p1 >= 0) {
        uint2 u = ((const uint2*)(g_y + ((size_t)g_topi[a0 + 1] * CAP + p1) * DMODEL))[t4];
        float2 fa = __half22float2(*(__half2*)&u.x);
        float2 fb = __half22float2(*(__half2*)&u.y);
        acc.x = fmaf(w1, fa.x, acc.x); acc.y = fmaf(w1, fa.y, acc.y);
        acc.z = fmaf(w1, fb.x, acc.z); acc.w = fmaf(w1, fb.y, acc.w);
    }
    if (ws > 0.f) {
        float inv = 1.f / fmaxf(ws, 1e-6f);
        acc.x *= inv; acc.y *= inv; acc.z *= inv; acc.w *= inv;
    }
    ((float4*)(out + (size_t)token * DMODEL))[t4] = acc;
}

// ---------------- launch ----------------
#define SMEM_TOTAL (NSTAGE * STAGE_BYTES)   // 64 KB per CTA

extern "C" void kernel_launch(void* const* d_in, const int* in_sizes, int n_in,
                              void* d_out, int out_size) {
    const float* x  = (const float*)d_in[0];
    const float* wr = (const float*)d_in[1];
    const float* br = (const float*)d_in[2];
    const float* w1 = (const float*)d_in[3];
    const float* b1 = (const float*)d_in[4];
    const float* w2 = (const float*)d_in[5];
    const float* b2 = (const float*)d_in[6];
    float* y = (float*)d_out;

    __half *buf, *h, *yy, *w1h, *w2h;
    cudaGetSymbolAddress((void**)&buf, g_buf);
    cudaGetSymbolAddress((void**)&h,   g_h);
    cudaGetSymbolAddress((void**)&yy,  g_y);
    cudaGetSymbolAddress((void**)&w1h, g_w1h);
    cudaGetSymbolAddress((void**)&w2h, g_w2h);

    cudaFuncSetAttribute(moe_mma_kernel, cudaFuncAttributeMaxDynamicSharedMemorySize, SMEM_TOTAL);

    // one-time side-stream + events for capture-legal fork/join (no device memory)
    static cudaStream_t s2 = nullptr;
    static cudaEvent_t evFork = nullptr, evJoin = nullptr;
    if (s2 == nullptr) {
        cudaStreamCreateWithFlags(&s2, cudaStreamNonBlocking);
        cudaEventCreateWithFlags(&evFork, cudaEventDisableTiming);
        cudaEventCreateWithFlags(&evJoin, cudaEventDisableTiming);
    }

    // fork: weight converts on s2, routing chain on origin stream (concurrent)
    cudaEventRecord(evFork, 0);
    cudaStreamWaitEvent(s2, evFork, 0);
    convert_w_kernel<<<dim3(FF / 32, DMODEL / 64, NEXP), 256, 0, s2>>>(w1, w1h, DMODEL, FF);
    convert_w_kernel<<<dim3(DMODEL / 32, FF / 64, NEXP), 256, 0, s2>>>(w2, w2h, FF, DMODEL);
    cudaEventRecord(evJoin, s2);

    router_kernel<<<NTOK / 8, 256>>>(x, wr, br);
    scan_count_kernel<<<8, 1024>>>();
    scan_scatter_kernel<<<8, 1024>>>();
    dispatch_kernel<<<NEXP * CAP, 256>>>(x);

    // join before GEMM1 (needs w1h + dispatched activations)
    cudaStreamWaitEvent(0, evJoin, 0);

    // GEMM1: h = fp16(GELU(buf @ w1 + b1))
    dim3 g1(FF / 128, CAP / 128, NEXP);       // 32 x 20 x 8
    moe_mma_kernel<<<g1, 256, SMEM_TOTAL>>>(buf, w1h, b1, (void*)h, FF, DMODEL, 3,
                              (long)CAP * DMODEL, (long)DMODEL * FF, FF, (long)CAP * FF);

    // GEMM2: y_e = fp16(h @ w2 + b2)
    dim3 g2(DMODEL / 128, CAP / 128, NEXP);   // 8 x 20 x 8
    moe_mma_kernel<<<g2, 256, SMEM_TOTAL>>>(h, w2h, b2, (void*)yy, DMODEL, FF, 2,
                              (long)CAP * FF, (long)FF * DMODEL, DMODEL, (long)CAP * DMODEL);

    combine_kernel<<<NTOK, 256>>>(y);
}